// round 1
// baseline (speedup 1.0000x reference)
#include <cuda_runtime.h>
#include <math.h>

#define NN 100000
#define FD 500
#define NC 64
#define KH 10
#define EMAX 3200000

// ---- scratch (no allocations allowed) ----
__device__ float g_bufA[(size_t)NN * NC];   // ping
__device__ float g_bufB[(size_t)NN * NC];   // pong
__device__ float g_hidden[(size_t)NN * NC]; // PPR accumulator
__device__ float g_deg[NN];
__device__ float g_dinv[NN];
__device__ float g_norm[EMAX];

// ---------------- degree / norm ----------------
__global__ void deg_init_kernel() {
    int i = blockIdx.x * blockDim.x + threadIdx.x;
    if (i < NN) g_deg[i] = 1.0f; // self loop
}

__global__ void deg_acc_kernel(const int* __restrict__ col, int E) {
    int e = blockIdx.x * blockDim.x + threadIdx.x;
    if (e < E) atomicAdd(&g_deg[col[e]], 1.0f);
}

__global__ void dinv_kernel() {
    int i = blockIdx.x * blockDim.x + threadIdx.x;
    if (i < NN) g_dinv[i] = rsqrtf(g_deg[i]);
}

__global__ void norm_kernel(const int* __restrict__ row, const int* __restrict__ col, int E) {
    int e = blockIdx.x * blockDim.x + threadIdx.x;
    if (e < E) g_norm[e] = g_dinv[row[e]] * g_dinv[col[e]];
}

// ---------------- fused MLP: h = relu(x@W1+b1)@W2 + b2 -> g_bufA ----------------
// 64 rows per block, 256 threads, 4x4 register tiles.
__global__ __launch_bounds__(256) void mlp_kernel(
    const float* __restrict__ x,
    const float* __restrict__ W1, const float* __restrict__ b1,
    const float* __restrict__ W2, const float* __restrict__ b2)
{
    __shared__ float As[8][68];    // [k][m], padded
    __shared__ float Bs[8][68];    // [k][n], padded
    __shared__ float Hs[64][65];   // h1 tile, padded
    __shared__ float W2s[64][64];
    __shared__ float bias2[64];

    const int t = threadIdx.x;
    const int row0 = blockIdx.x * 64;
    const int ty = t >> 4;   // 0..15 (4 rows each)
    const int tx = t & 15;   // 0..15 (4 cols each)

    // preload W2 / b2
    for (int i = t; i < 64 * 64; i += 256) W2s[i >> 6][i & 63] = W2[i];
    if (t < 64) bias2[t] = b2[t];

    float acc[4][4];
#pragma unroll
    for (int i = 0; i < 4; i++)
#pragma unroll
        for (int j = 0; j < 4; j++) acc[i][j] = 0.0f;

    // load assignment for X: thread t -> row m = t>>2, float2 at k-offset (t&3)*2
    const int lm = t >> 2;
    const int lq = t & 3;

    for (int k0 = 0; k0 < FD; k0 += 8) {
        // --- stage X tile (64 rows x 8 k) ---
        {
            int gr = row0 + lm;
            int gk = k0 + lq * 2;
            float2 xv = make_float2(0.0f, 0.0f);
            if (gr < NN && gk + 1 < FD) {
                xv = *reinterpret_cast<const float2*>(&x[(size_t)gr * FD + gk]);
            } else if (gr < NN && gk < FD) {
                xv.x = x[(size_t)gr * FD + gk];
            }
            As[lq * 2 + 0][lm] = xv.x;
            As[lq * 2 + 1][lm] = xv.y;
        }
        // --- stage W1 tile (8 k x 64 n) ---
        {
#pragma unroll
            for (int j = 0; j < 2; j++) {
                int idx = t + j * 256;
                int n = idx & 63, kl = idx >> 6;
                int gk = k0 + kl;
                Bs[kl][n] = (gk < FD) ? W1[gk * 64 + n] : 0.0f;
            }
        }
        __syncthreads();

#pragma unroll
        for (int kl = 0; kl < 8; kl++) {
            float4 a = *reinterpret_cast<const float4*>(&As[kl][ty * 4]);
            float4 b = *reinterpret_cast<const float4*>(&Bs[kl][tx * 4]);
            float av[4] = {a.x, a.y, a.z, a.w};
            float bv[4] = {b.x, b.y, b.z, b.w};
#pragma unroll
            for (int i = 0; i < 4; i++)
#pragma unroll
                for (int j = 0; j < 4; j++) acc[i][j] += av[i] * bv[j];
        }
        __syncthreads();
    }

    // bias1 + relu -> Hs
    float bb[4];
#pragma unroll
    for (int j = 0; j < 4; j++) bb[j] = b1[tx * 4 + j];
#pragma unroll
    for (int i = 0; i < 4; i++)
#pragma unroll
        for (int j = 0; j < 4; j++) {
            float v = acc[i][j] + bb[j];
            Hs[ty * 4 + i][tx * 4 + j] = v > 0.0f ? v : 0.0f;
        }
    __syncthreads();

    // second GEMM: (64x64) @ (64x64)
    float acc2[4][4];
#pragma unroll
    for (int i = 0; i < 4; i++)
#pragma unroll
        for (int j = 0; j < 4; j++) acc2[i][j] = 0.0f;

#pragma unroll 8
    for (int k = 0; k < 64; k++) {
        float av[4], bv[4];
        float4 b = *reinterpret_cast<const float4*>(&W2s[k][tx * 4]);
        bv[0] = b.x; bv[1] = b.y; bv[2] = b.z; bv[3] = b.w;
#pragma unroll
        for (int i = 0; i < 4; i++) av[i] = Hs[ty * 4 + i][k];
#pragma unroll
        for (int i = 0; i < 4; i++)
#pragma unroll
            for (int j = 0; j < 4; j++) acc2[i][j] += av[i] * bv[j];
    }

    // store to g_bufA
#pragma unroll
    for (int i = 0; i < 4; i++) {
        int gr = row0 + ty * 4 + i;
        if (gr < NN) {
            float4 v;
            v.x = acc2[i][0] + bias2[tx * 4 + 0];
            v.y = acc2[i][1] + bias2[tx * 4 + 1];
            v.z = acc2[i][2] + bias2[tx * 4 + 2];
            v.w = acc2[i][3] + bias2[tx * 4 + 3];
            *reinterpret_cast<float4*>(&g_bufA[(size_t)gr * NC + tx * 4]) = v;
        }
    }
}

// ---------------- per-hop init: out = dinv^2 * cur ; hidden (+)= temp[k]*cur ----------------
__global__ void init_hop_kernel(const float* __restrict__ temp, int k, int flip) {
    const float* cur = flip ? g_bufB : g_bufA;
    float* out = flip ? g_bufA : g_bufB;
    int idx = blockIdx.x * blockDim.x + threadIdx.x; // over NN*16 float4s
    if (idx >= NN * 16) return;
    int node = idx >> 4;
    float d = g_dinv[node];
    float d2 = d * d;
    float tk = temp[k];
    float4 v = reinterpret_cast<const float4*>(cur)[idx];
    float4 o = make_float4(d2 * v.x, d2 * v.y, d2 * v.z, d2 * v.w);
    reinterpret_cast<float4*>(out)[idx] = o;
    float4* hp = reinterpret_cast<float4*>(g_hidden);
    if (k == 0) {
        hp[idx] = make_float4(tk * v.x, tk * v.y, tk * v.z, tk * v.w);
    } else {
        float4 h = hp[idx];
        h.x += tk * v.x; h.y += tk * v.y; h.z += tk * v.z; h.w += tk * v.w;
        hp[idx] = h;
    }
}

// ---------------- edge scatter: out[col] += norm * cur[row] ----------------
// 16 threads per edge, one float4 each; vector reduction (red.global.add.v4.f32)
__global__ __launch_bounds__(256) void scatter_kernel(
    const int* __restrict__ row, const int* __restrict__ col, int E, int flip)
{
    const float* cur = flip ? g_bufB : g_bufA;
    float* out = flip ? g_bufA : g_bufB;
    long long gid = (long long)blockIdx.x * blockDim.x + threadIdx.x;
    int e = (int)(gid >> 4);
    if (e >= E) return;
    int c = (int)(gid & 15);
    int r = __ldg(&row[e]);
    int co = __ldg(&col[e]);
    float w = g_norm[e];
    float4 v = reinterpret_cast<const float4*>(cur)[(size_t)r * 16 + c];
    float sx = v.x * w, sy = v.y * w, sz = v.z * w, sw = v.w * w;
    float* p = out + ((size_t)co * NC + c * 4);
    asm volatile("red.global.add.v4.f32 [%0], {%1,%2,%3,%4};"
                 :: "l"(p), "f"(sx), "f"(sy), "f"(sz), "f"(sw) : "memory");
}

// ---------------- final: hidden += temp[K]*cur ; log_softmax -> d_out ----------------
__global__ void final_kernel(const float* __restrict__ temp, float* __restrict__ out, int flip) {
    const float* cur = flip ? g_bufB : g_bufA;
    int warp = (blockIdx.x * blockDim.x + threadIdx.x) >> 5;
    int lane = threadIdx.x & 31;
    if (warp >= NN) return;
    float tK = temp[KH];
    size_t base = (size_t)warp * NC;
    float a = g_hidden[base + lane] + tK * cur[base + lane];
    float b = g_hidden[base + 32 + lane] + tK * cur[base + 32 + lane];
    float mx = fmaxf(a, b);
#pragma unroll
    for (int off = 16; off > 0; off >>= 1)
        mx = fmaxf(mx, __shfl_xor_sync(0xFFFFFFFFu, mx, off));
    float s = expf(a - mx) + expf(b - mx);
#pragma unroll
    for (int off = 16; off > 0; off >>= 1)
        s += __shfl_xor_sync(0xFFFFFFFFu, s, off);
    float l = mx + logf(s);
    out[base + lane] = a - l;
    out[base + 32 + lane] = b - l;
}

// ---------------- launch ----------------
extern "C" void kernel_launch(void* const* d_in, const int* in_sizes, int n_in,
                              void* d_out, int out_size)
{
    const float* x   = (const float*)d_in[0];
    const int*   ei  = (const int*)d_in[1];
    const float* W1  = (const float*)d_in[2];
    const float* b1  = (const float*)d_in[3];
    const float* W2  = (const float*)d_in[4];
    const float* b2  = (const float*)d_in[5];
    const float* temp= (const float*)d_in[6];
    float* out = (float*)d_out;

    const int E = in_sizes[1] / 2;
    const int* row = ei;       // source
    const int* col = ei + E;   // target

    // degrees + norm
    deg_init_kernel<<<(NN + 255) / 256, 256>>>();
    deg_acc_kernel<<<(E + 255) / 256, 256>>>(col, E);
    dinv_kernel<<<(NN + 255) / 256, 256>>>();
    norm_kernel<<<(E + 255) / 256, 256>>>(row, col, E);

    // MLP -> g_bufA
    mlp_kernel<<<(NN + 63) / 64, 256>>>(x, W1, b1, W2, b2);

    // propagation
    long long sthreads = (long long)E * 16;
    int sblocks = (int)((sthreads + 255) / 256);
    for (int k = 0; k < KH; k++) {
        int flip = k & 1;
        init_hop_kernel<<<(NN * 16 + 255) / 256, 256>>>(temp, k, flip);
        scatter_kernel<<<sblocks, 256>>>(row, col, E, flip);
    }

    // KH even -> final cur lives in g_bufA (flip=0)
    final_kernel<<<(NN + 7) / 8, 256>>>(temp, out, KH & 1);
}

// round 3
// speedup vs baseline: 2.3439x; 2.3439x over previous
#include <cuda_runtime.h>
#include <math.h>

#define NN 100000
#define FD 500
#define NC 64
#define KH 10
#define EMAX 3200000
#define NB_SCAN ((NN + 1023) / 1024)

// ---- scratch (no allocations allowed) ----
__device__ float g_bufA[(size_t)NN * NC];   // ping (scaled y)
__device__ float g_bufB[(size_t)NN * NC];   // pong
__device__ float g_hidden[(size_t)NN * NC]; // scaled PPR accumulator hs = dinv*hidden
__device__ float g_dinv[NN];
__device__ float g_sdeg[NN];
__device__ int   g_cnt[NN];
__device__ int   g_cursor[NN];
__device__ int   g_off[NN + 1];
__device__ int   g_bsum[NB_SCAN];
__device__ int   g_src[EMAX];

// ---------------- in-degree count ----------------
__global__ void cnt_zero_kernel() {
    int i = blockIdx.x * blockDim.x + threadIdx.x;
    if (i < NN) g_cnt[i] = 0;
}

__global__ void cnt_acc_kernel(const int* __restrict__ col, int E) {
    int e = blockIdx.x * blockDim.x + threadIdx.x;
    if (e < E) atomicAdd(&g_cnt[col[e]], 1);
}

// ---------------- scan: block-local exclusive scan + dinv/sdeg/cursor ----------------
__global__ __launch_bounds__(1024) void scan1_kernel() {
    __shared__ int sh[1024];
    int i = blockIdx.x * 1024 + threadIdx.x;
    int v = (i < NN) ? g_cnt[i] : 0;
    sh[threadIdx.x] = v;
    __syncthreads();
#pragma unroll
    for (int off = 1; off < 1024; off <<= 1) {
        int t = 0;
        if (threadIdx.x >= off) t = sh[threadIdx.x - off];
        __syncthreads();
        if (threadIdx.x >= off) sh[threadIdx.x] += t;
        __syncthreads();
    }
    if (i < NN) {
        g_off[i] = sh[threadIdx.x] - v;           // exclusive, block-local
        float deg = (float)(v + 1);               // + self loop
        g_dinv[i] = rsqrtf(deg);
        g_sdeg[i] = sqrtf(deg);
        g_cursor[i] = 0;
    }
    if (threadIdx.x == 1023) g_bsum[blockIdx.x] = sh[1023];
}

__global__ void scan2_kernel() {
    if (threadIdx.x == 0 && blockIdx.x == 0) {
        int running = 0;
        for (int b = 0; b < NB_SCAN; b++) {
            int t = g_bsum[b];
            g_bsum[b] = running;
            running += t;
        }
        g_off[NN] = running;
    }
}

__global__ __launch_bounds__(1024) void scan3_kernel() {
    int i = blockIdx.x * 1024 + threadIdx.x;
    if (i < NN) g_off[i] += g_bsum[blockIdx.x];
}

// ---------------- CSR fill ----------------
__global__ void fill_kernel(const int* __restrict__ row, const int* __restrict__ col, int E) {
    int e = blockIdx.x * blockDim.x + threadIdx.x;
    if (e < E) {
        int c = col[e];
        int p = atomicAdd(&g_cursor[c], 1);
        g_src[g_off[c] + p] = row[e];
    }
}

// ---------------- fused MLP: y0 = dinv*(relu(x@W1+b1)@W2 + b2) -> g_bufA ----------------
__global__ __launch_bounds__(256) void mlp_kernel(
    const float* __restrict__ x,
    const float* __restrict__ W1, const float* __restrict__ b1,
    const float* __restrict__ W2, const float* __restrict__ b2,
    const float* __restrict__ temp)
{
    __shared__ float As[8][68];
    __shared__ float Bs[8][68];
    __shared__ float Hs[64][65];
    __shared__ float W2s[64][64];
    __shared__ float bias2[64];

    const int t = threadIdx.x;
    const int row0 = blockIdx.x * 64;
    const int ty = t >> 4;
    const int tx = t & 15;

    for (int i = t; i < 64 * 64; i += 256) W2s[i >> 6][i & 63] = W2[i];
    if (t < 64) bias2[t] = b2[t];

    float acc[4][4];
#pragma unroll
    for (int i = 0; i < 4; i++)
#pragma unroll
        for (int j = 0; j < 4; j++) acc[i][j] = 0.0f;

    const int lm = t >> 2;
    const int lq = t & 3;

    for (int k0 = 0; k0 < FD; k0 += 8) {
        {
            int gr = row0 + lm;
            int gk = k0 + lq * 2;
            float2 xv = make_float2(0.0f, 0.0f);
            if (gr < NN && gk + 1 < FD) {
                xv = *reinterpret_cast<const float2*>(&x[(size_t)gr * FD + gk]);
            } else if (gr < NN && gk < FD) {
                xv.x = x[(size_t)gr * FD + gk];
            }
            As[lq * 2 + 0][lm] = xv.x;
            As[lq * 2 + 1][lm] = xv.y;
        }
        {
#pragma unroll
            for (int j = 0; j < 2; j++) {
                int idx = t + j * 256;
                int n = idx & 63, kl = idx >> 6;
                int gk = k0 + kl;
                Bs[kl][n] = (gk < FD) ? W1[gk * 64 + n] : 0.0f;
            }
        }
        __syncthreads();

#pragma unroll
        for (int kl = 0; kl < 8; kl++) {
            float4 a = *reinterpret_cast<const float4*>(&As[kl][ty * 4]);
            float4 b = *reinterpret_cast<const float4*>(&Bs[kl][tx * 4]);
            float av[4] = {a.x, a.y, a.z, a.w};
            float bv[4] = {b.x, b.y, b.z, b.w};
#pragma unroll
            for (int i = 0; i < 4; i++)
#pragma unroll
                for (int j = 0; j < 4; j++) acc[i][j] += av[i] * bv[j];
        }
        __syncthreads();
    }

    float bb[4];
#pragma unroll
    for (int j = 0; j < 4; j++) bb[j] = b1[tx * 4 + j];
#pragma unroll
    for (int i = 0; i < 4; i++)
#pragma unroll
        for (int j = 0; j < 4; j++) {
            float v = acc[i][j] + bb[j];
            Hs[ty * 4 + i][tx * 4 + j] = v > 0.0f ? v : 0.0f;
        }
    __syncthreads();

    float acc2[4][4];
#pragma unroll
    for (int i = 0; i < 4; i++)
#pragma unroll
        for (int j = 0; j < 4; j++) acc2[i][j] = 0.0f;

#pragma unroll 8
    for (int k = 0; k < 64; k++) {
        float av[4], bv[4];
        float4 b = *reinterpret_cast<const float4*>(&W2s[k][tx * 4]);
        bv[0] = b.x; bv[1] = b.y; bv[2] = b.z; bv[3] = b.w;
#pragma unroll
        for (int i = 0; i < 4; i++) av[i] = Hs[ty * 4 + i][k];
#pragma unroll
        for (int i = 0; i < 4; i++)
#pragma unroll
            for (int j = 0; j < 4; j++) acc2[i][j] += av[i] * bv[j];
    }

    float t0 = temp[0];
#pragma unroll
    for (int i = 0; i < 4; i++) {
        int gr = row0 + ty * 4 + i;
        if (gr < NN) {
            float d = g_dinv[gr];
            float4 v;
            v.x = d * (acc2[i][0] + bias2[tx * 4 + 0]);
            v.y = d * (acc2[i][1] + bias2[tx * 4 + 1]);
            v.z = d * (acc2[i][2] + bias2[tx * 4 + 2]);
            v.w = d * (acc2[i][3] + bias2[tx * 4 + 3]);
            *reinterpret_cast<float4*>(&g_bufA[(size_t)gr * NC + tx * 4]) = v;
            float4 h = make_float4(t0 * v.x, t0 * v.y, t0 * v.z, t0 * v.w);
            *reinterpret_cast<float4*>(&g_hidden[(size_t)gr * NC + tx * 4]) = h;
        }
    }
}

// ---------------- pull propagation: warp per node ----------------
// y_{k+1}[c] = d^2 * ( sum_{r in N_in(c)} y_k[r] + y_k[c] );  hs += temp[k+1]*y_{k+1}
__global__ __launch_bounds__(256) void propagate_kernel(const float* __restrict__ temp, int k, int flip) {
    const float* __restrict__ y = flip ? g_bufB : g_bufA;
    float* __restrict__ yn = flip ? g_bufA : g_bufB;
    int node = (blockIdx.x * blockDim.x + threadIdx.x) >> 5;
    int lane = threadIdx.x & 31;
    if (node >= NN) return;

    float d = g_dinv[node];
    size_t base = (size_t)node * NC + lane * 2;
    float2 self = *reinterpret_cast<const float2*>(&y[base]);
    float ax = self.x, ay = self.y;   // self-loop term: + y_k[c]  (no extra d!)

    int beg = g_off[node];
    int end = g_off[node + 1];
    for (int i = beg; i < end; i += 32) {
        int n = end - i;
        n = n < 32 ? n : 32;
        int s = (lane < n) ? __ldg(&g_src[i + lane]) : 0;
        for (int j = 0; j < n; j++) {
            int sj = __shfl_sync(0xFFFFFFFFu, s, j);
            float2 v = *reinterpret_cast<const float2*>(&y[(size_t)sj * NC + lane * 2]);
            ax += v.x;
            ay += v.y;
        }
    }

    float d2 = d * d;
    float ox = d2 * ax, oy = d2 * ay;
    *reinterpret_cast<float2*>(&yn[base]) = make_float2(ox, oy);

    float tk = temp[k + 1];
    float2 h = *reinterpret_cast<float2*>(&g_hidden[base]);
    h.x += tk * ox;
    h.y += tk * oy;
    *reinterpret_cast<float2*>(&g_hidden[base]) = h;
}

// ---------------- final: out = log_softmax(hs * sqrt(deg)) ----------------
__global__ void final_kernel(float* __restrict__ out) {
    int warp = (blockIdx.x * blockDim.x + threadIdx.x) >> 5;
    int lane = threadIdx.x & 31;
    if (warp >= NN) return;
    float sd = g_sdeg[warp];
    size_t base = (size_t)warp * NC;
    float a = g_hidden[base + lane] * sd;
    float b = g_hidden[base + 32 + lane] * sd;
    float mx = fmaxf(a, b);
#pragma unroll
    for (int off = 16; off > 0; off >>= 1)
        mx = fmaxf(mx, __shfl_xor_sync(0xFFFFFFFFu, mx, off));
    float s = expf(a - mx) + expf(b - mx);
#pragma unroll
    for (int off = 16; off > 0; off >>= 1)
        s += __shfl_xor_sync(0xFFFFFFFFu, s, off);
    float l = mx + logf(s);
    out[base + lane] = a - l;
    out[base + 32 + lane] = b - l;
}

// ---------------- launch ----------------
extern "C" void kernel_launch(void* const* d_in, const int* in_sizes, int n_in,
                              void* d_out, int out_size)
{
    const float* x    = (const float*)d_in[0];
    const int*   ei   = (const int*)d_in[1];
    const float* W1   = (const float*)d_in[2];
    const float* b1   = (const float*)d_in[3];
    const float* W2   = (const float*)d_in[4];
    const float* b2   = (const float*)d_in[5];
    const float* temp = (const float*)d_in[6];
    float* out = (float*)d_out;

    const int E = in_sizes[1] / 2;
    const int* row = ei;       // source
    const int* col = ei + E;   // target

    // CSR build
    cnt_zero_kernel<<<(NN + 255) / 256, 256>>>();
    cnt_acc_kernel<<<(E + 255) / 256, 256>>>(col, E);
    scan1_kernel<<<NB_SCAN, 1024>>>();
    scan2_kernel<<<1, 32>>>();
    scan3_kernel<<<NB_SCAN, 1024>>>();
    fill_kernel<<<(E + 255) / 256, 256>>>(row, col, E);

    // MLP -> y0 in g_bufA, hs init in g_hidden
    mlp_kernel<<<(NN + 63) / 64, 256>>>(x, W1, b1, W2, b2, temp);

    // pull propagation: 1 warp per node
    int pblocks = (NN * 32 + 255) / 256;
    for (int k = 0; k < KH; k++) {
        propagate_kernel<<<pblocks, 256>>>(temp, k, k & 1);
    }

    final_kernel<<<(NN * 32 + 255) / 256, 256>>>(out);
}

// round 4
// speedup vs baseline: 2.4414x; 1.0416x over previous
#include <cuda_runtime.h>
#include <cuda_fp16.h>
#include <math.h>

#define NN 100000
#define FD 500
#define NC 64
#define KH 10
#define EMAX 3200000
#define NB_SCAN ((NN + 1023) / 1024)

// ---- scratch (no allocations allowed) ----
__device__ __half2 g_yA[(size_t)NN * 32];   // ping: scaled y, fp16, 32 half2 per node
__device__ __half2 g_yB[(size_t)NN * 32];   // pong
__device__ float g_hidden[(size_t)NN * NC]; // scaled PPR accumulator (fp32)
__device__ float g_dinv[NN];
__device__ float g_sdeg[NN];
__device__ int   g_cnt[NN];
__device__ int   g_cursor[NN];
__device__ int   g_off[NN + 1];
__device__ int   g_bsum[NB_SCAN];
__device__ int   g_src[EMAX];

// ---------------- in-degree count ----------------
__global__ void cnt_zero_kernel() {
    int i = blockIdx.x * blockDim.x + threadIdx.x;
    if (i < NN) g_cnt[i] = 0;
}

__global__ void cnt_acc_kernel(const int* __restrict__ col, int E) {
    int e = blockIdx.x * blockDim.x + threadIdx.x;
    if (e < E) atomicAdd(&g_cnt[col[e]], 1);
}

// ---------------- scan: block-local exclusive scan + dinv/sdeg/cursor ----------------
__global__ __launch_bounds__(1024) void scan1_kernel() {
    __shared__ int sh[1024];
    int i = blockIdx.x * 1024 + threadIdx.x;
    int v = (i < NN) ? g_cnt[i] : 0;
    sh[threadIdx.x] = v;
    __syncthreads();
#pragma unroll
    for (int off = 1; off < 1024; off <<= 1) {
        int t = 0;
        if (threadIdx.x >= off) t = sh[threadIdx.x - off];
        __syncthreads();
        if (threadIdx.x >= off) sh[threadIdx.x] += t;
        __syncthreads();
    }
    if (i < NN) {
        g_off[i] = sh[threadIdx.x] - v;           // exclusive, block-local
        float deg = (float)(v + 1);               // + self loop
        g_dinv[i] = rsqrtf(deg);
        g_sdeg[i] = sqrtf(deg);
        g_cursor[i] = 0;
    }
    if (threadIdx.x == 1023) g_bsum[blockIdx.x] = sh[1023];
}

__global__ void scan2_kernel() {
    if (threadIdx.x == 0 && blockIdx.x == 0) {
        int running = 0;
        for (int b = 0; b < NB_SCAN; b++) {
            int t = g_bsum[b];
            g_bsum[b] = running;
            running += t;
        }
        g_off[NN] = running;
    }
}

__global__ __launch_bounds__(1024) void scan3_kernel() {
    int i = blockIdx.x * 1024 + threadIdx.x;
    if (i < NN) g_off[i] += g_bsum[blockIdx.x];
}

// ---------------- CSR fill ----------------
__global__ void fill_kernel(const int* __restrict__ row, const int* __restrict__ col, int E) {
    int e = blockIdx.x * blockDim.x + threadIdx.x;
    if (e < E) {
        int c = col[e];
        int p = atomicAdd(&g_cursor[c], 1);
        g_src[g_off[c] + p] = row[e];
    }
}

// ---------------- fused MLP: y0 = dinv*(relu(x@W1+b1)@W2 + b2) ----------------
// fp32 compute; writes y0 to g_yA (fp16) and temp[0]*y0 to g_hidden (fp32)
__global__ __launch_bounds__(256) void mlp_kernel(
    const float* __restrict__ x,
    const float* __restrict__ W1, const float* __restrict__ b1,
    const float* __restrict__ W2, const float* __restrict__ b2,
    const float* __restrict__ temp)
{
    __shared__ float As[8][68];
    __shared__ float Bs[8][68];
    __shared__ float Hs[64][65];
    __shared__ float W2s[64][64];
    __shared__ float bias2[64];

    const int t = threadIdx.x;
    const int row0 = blockIdx.x * 64;
    const int ty = t >> 4;
    const int tx = t & 15;

    for (int i = t; i < 64 * 64; i += 256) W2s[i >> 6][i & 63] = W2[i];
    if (t < 64) bias2[t] = b2[t];

    float acc[4][4];
#pragma unroll
    for (int i = 0; i < 4; i++)
#pragma unroll
        for (int j = 0; j < 4; j++) acc[i][j] = 0.0f;

    const int lm = t >> 2;
    const int lq = t & 3;

    for (int k0 = 0; k0 < FD; k0 += 8) {
        {
            int gr = row0 + lm;
            int gk = k0 + lq * 2;
            float2 xv = make_float2(0.0f, 0.0f);
            if (gr < NN && gk + 1 < FD) {
                xv = *reinterpret_cast<const float2*>(&x[(size_t)gr * FD + gk]);
            } else if (gr < NN && gk < FD) {
                xv.x = x[(size_t)gr * FD + gk];
            }
            As[lq * 2 + 0][lm] = xv.x;
            As[lq * 2 + 1][lm] = xv.y;
        }
        {
#pragma unroll
            for (int j = 0; j < 2; j++) {
                int idx = t + j * 256;
                int n = idx & 63, kl = idx >> 6;
                int gk = k0 + kl;
                Bs[kl][n] = (gk < FD) ? W1[gk * 64 + n] : 0.0f;
            }
        }
        __syncthreads();

#pragma unroll
        for (int kl = 0; kl < 8; kl++) {
            float4 a = *reinterpret_cast<const float4*>(&As[kl][ty * 4]);
            float4 b = *reinterpret_cast<const float4*>(&Bs[kl][tx * 4]);
            float av[4] = {a.x, a.y, a.z, a.w};
            float bv[4] = {b.x, b.y, b.z, b.w};
#pragma unroll
            for (int i = 0; i < 4; i++)
#pragma unroll
                for (int j = 0; j < 4; j++) acc[i][j] += av[i] * bv[j];
        }
        __syncthreads();
    }

    float bb[4];
#pragma unroll
    for (int j = 0; j < 4; j++) bb[j] = b1[tx * 4 + j];
#pragma unroll
    for (int i = 0; i < 4; i++)
#pragma unroll
        for (int j = 0; j < 4; j++) {
            float v = acc[i][j] + bb[j];
            Hs[ty * 4 + i][tx * 4 + j] = v > 0.0f ? v : 0.0f;
        }
    __syncthreads();

    float acc2[4][4];
#pragma unroll
    for (int i = 0; i < 4; i++)
#pragma unroll
        for (int j = 0; j < 4; j++) acc2[i][j] = 0.0f;

#pragma unroll 8
    for (int k = 0; k < 64; k++) {
        float av[4], bv[4];
        float4 b = *reinterpret_cast<const float4*>(&W2s[k][tx * 4]);
        bv[0] = b.x; bv[1] = b.y; bv[2] = b.z; bv[3] = b.w;
#pragma unroll
        for (int i = 0; i < 4; i++) av[i] = Hs[ty * 4 + i][k];
#pragma unroll
        for (int i = 0; i < 4; i++)
#pragma unroll
            for (int j = 0; j < 4; j++) acc2[i][j] += av[i] * bv[j];
    }

    float t0 = temp[0];
#pragma unroll
    for (int i = 0; i < 4; i++) {
        int gr = row0 + ty * 4 + i;
        if (gr < NN) {
            float d = g_dinv[gr];
            float4 v;
            v.x = d * (acc2[i][0] + bias2[tx * 4 + 0]);
            v.y = d * (acc2[i][1] + bias2[tx * 4 + 1]);
            v.z = d * (acc2[i][2] + bias2[tx * 4 + 2]);
            v.w = d * (acc2[i][3] + bias2[tx * 4 + 3]);
            // y0 in fp16 (2x half2)
            g_yA[(size_t)gr * 32 + tx * 2 + 0] = __floats2half2_rn(v.x, v.y);
            g_yA[(size_t)gr * 32 + tx * 2 + 1] = __floats2half2_rn(v.z, v.w);
            float4 h = make_float4(t0 * v.x, t0 * v.y, t0 * v.z, t0 * v.w);
            *reinterpret_cast<float4*>(&g_hidden[(size_t)gr * NC + tx * 4]) = h;
        }
    }
}

// ---------------- pull propagation: warp per node, fp16 gather, fp32 accumulate ----------------
// y_{k+1}[c] = d^2 * ( sum_{r in N_in(c)} y_k[r] + y_k[c] );  hs += temp[k+1]*y_{k+1}
__global__ __launch_bounds__(256) void propagate_kernel(const float* __restrict__ temp, int k, int flip) {
    const __half2* __restrict__ y = flip ? g_yB : g_yA;
    __half2* __restrict__ yn = flip ? g_yA : g_yB;
    int node = (blockIdx.x * blockDim.x + threadIdx.x) >> 5;
    int lane = threadIdx.x & 31;
    if (node >= NN) return;

    float d = g_dinv[node];
    size_t base2 = (size_t)node * 32 + lane;
    float2 self = __half22float2(y[base2]);
    float ax = self.x, ay = self.y;   // self-loop term: + y_k[c]

    int beg = g_off[node];
    int end = g_off[node + 1];
    int nfull = (end - beg) & ~31;
    int i = beg;
    for (; i < beg + nfull; i += 32) {
        int s = __ldg(&g_src[i + lane]);
#pragma unroll
        for (int j = 0; j < 32; j++) {
            int sj = __shfl_sync(0xFFFFFFFFu, s, j);
            float2 v = __half22float2(__ldg(&y[(size_t)sj * 32 + lane]));
            ax += v.x;
            ay += v.y;
        }
    }
    if (i < end) {
        int n = end - i;
        int s = (lane < n) ? __ldg(&g_src[i + lane]) : 0;
        for (int j = 0; j < n; j++) {
            int sj = __shfl_sync(0xFFFFFFFFu, s, j);
            float2 v = __half22float2(__ldg(&y[(size_t)sj * 32 + lane]));
            ax += v.x;
            ay += v.y;
        }
    }

    float d2 = d * d;
    float ox = d2 * ax, oy = d2 * ay;
    yn[base2] = __floats2half2_rn(ox, oy);

    float tk = temp[k + 1];
    float2 h = *reinterpret_cast<float2*>(&g_hidden[(size_t)node * NC + lane * 2]);
    h.x += tk * ox;
    h.y += tk * oy;
    *reinterpret_cast<float2*>(&g_hidden[(size_t)node * NC + lane * 2]) = h;
}

// ---------------- final: out = log_softmax(hs * sqrt(deg)) ----------------
__global__ void final_kernel(float* __restrict__ out) {
    int warp = (blockIdx.x * blockDim.x + threadIdx.x) >> 5;
    int lane = threadIdx.x & 31;
    if (warp >= NN) return;
    float sd = g_sdeg[warp];
    size_t base = (size_t)warp * NC;
    float a = g_hidden[base + lane] * sd;
    float b = g_hidden[base + 32 + lane] * sd;
    float mx = fmaxf(a, b);
#pragma unroll
    for (int off = 16; off > 0; off >>= 1)
        mx = fmaxf(mx, __shfl_xor_sync(0xFFFFFFFFu, mx, off));
    float s = expf(a - mx) + expf(b - mx);
#pragma unroll
    for (int off = 16; off > 0; off >>= 1)
        s += __shfl_xor_sync(0xFFFFFFFFu, s, off);
    float l = mx + logf(s);
    out[base + lane] = a - l;
    out[base + 32 + lane] = b - l;
}

// ---------------- launch ----------------
extern "C" void kernel_launch(void* const* d_in, const int* in_sizes, int n_in,
                              void* d_out, int out_size)
{
    const float* x    = (const float*)d_in[0];
    const int*   ei   = (const int*)d_in[1];
    const float* W1   = (const float*)d_in[2];
    const float* b1   = (const float*)d_in[3];
    const float* W2   = (const float*)d_in[4];
    const float* b2   = (const float*)d_in[5];
    const float* temp = (const float*)d_in[6];
    float* out = (float*)d_out;

    const int E = in_sizes[1] / 2;
    const int* row = ei;       // source
    const int* col = ei + E;   // target

    // CSR build
    cnt_zero_kernel<<<(NN + 255) / 256, 256>>>();
    cnt_acc_kernel<<<(E + 255) / 256, 256>>>(col, E);
    scan1_kernel<<<NB_SCAN, 1024>>>();
    scan2_kernel<<<1, 32>>>();
    scan3_kernel<<<NB_SCAN, 1024>>>();
    fill_kernel<<<(E + 255) / 256, 256>>>(row, col, E);

    // MLP -> y0 in g_yA (fp16), hs init in g_hidden (fp32)
    mlp_kernel<<<(NN + 63) / 64, 256>>>(x, W1, b1, W2, b2, temp);

    // pull propagation: 1 warp per node
    int pblocks = (NN * 32 + 255) / 256;
    for (int k = 0; k < KH; k++) {
        propagate_kernel<<<pblocks, 256>>>(temp, k, k & 1);
    }

    final_kernel<<<(NN * 32 + 255) / 256, 256>>>(out);
}